// round 3
// baseline (speedup 1.0000x reference)
#include <cuda_runtime.h>

#define NN 2048
#define EE 16384
#define DIN 1280
#define ROWW 64            // uint32 words per 2048-bit ego row
#define MAXDEG 64          // fixed-stride CSR slot capacity
#define NEGBIG (-1e30f)

// -------- device scratch (no allocation allowed) --------
__device__ float    g_h[NN];                 // h = x_orig @ W2^T
__device__ unsigned g_rowM[NN * ROWW];       // row-major ego bitmasks (256B/ego)
__device__ int      g_deg[NN];               // in-degree counters
__device__ int      g_nsrc[NN * MAXDEG];     // in-edge source ids, per dst
__device__ float    g_nh[NN * MAXDEG];       // h[src] payload, per dst
__device__ float4   g_edge[NN * MAXDEG];     // {src_bits, w, wh, pad} packed per edge
__device__ float4   g_self[NN];              // {self_w, self_wh, deg_f, h_i}

// ---------------- h = x_orig @ W2^T (one warp per row) + zero scratch ----------------
__global__ void k_h(const float* __restrict__ xo, const float* __restrict__ W2) {
    int warp = (blockIdx.x * blockDim.x + threadIdx.x) >> 5;
    int lane = threadIdx.x & 31;
    const float4* xr = (const float4*)(xo + (size_t)warp * DIN);
    const float4* wr = (const float4*)W2;
    float acc = 0.f;
#pragma unroll
    for (int i = 0; i < DIN / 128; i++) {     // 10 float4 per lane
        float4 a = xr[lane + i * 32];
        float4 b = wr[lane + i * 32];
        acc += a.x * b.x + a.y * b.y + a.z * b.z + a.w * b.w;
    }
#pragma unroll
    for (int off = 16; off; off >>= 1) acc += __shfl_xor_sync(0xffffffffu, acc, off);
    if (lane == 0) {
        g_h[warp] = acc;
        g_deg[warp] = 0;
    }
    g_rowM[(size_t)warp * ROWW + lane]      = 0u;
    g_rowM[(size_t)warp * ROWW + 32 + lane] = 0u;
}

// ---------------- fixed-stride in-edge CSR scatter ----------------
__global__ void k_scatter(const int* __restrict__ ei) {
    int e = blockIdx.x * blockDim.x + threadIdx.x;
    if (e < EE) {
        int s = ei[e];
        int d = ei[EE + e];
        int p = atomicAdd(&g_deg[d], 1);
        if (p < MAXDEG) {
            g_nsrc[d * MAXDEG + p] = s;
            g_nh[d * MAXDEG + p]   = g_h[s];
        }
    }
}

// ------- fused: sparse 2-hop masks (warp/ego) + per-node edge precompute -------
__global__ void k_hops_pre(const float* __restrict__ att_src,
                           const float* __restrict__ att_dst) {
    int gtid = blockIdx.x * blockDim.x + threadIdx.x;
    int warp = gtid >> 5;
    int lane = threadIdx.x & 31;

    // ---- part A: 2-hop ego mask, one warp per ego ----
    {
        int v = warp;
        unsigned* row = g_rowM + (size_t)v * ROWW;
        if (lane == 0) atomicOr(&row[v >> 5], 1u << (v & 31));
        int dv = min(g_deg[v], MAXDEG);
        for (int k = lane; k < dv; k += 32) {
            int s = g_nsrc[v * MAXDEG + k];
            atomicOr(&row[s >> 5], 1u << (s & 31));
            int ds = min(g_deg[s], MAXDEG);
            for (int j = 0; j < ds; j++) {
                int t = g_nsrc[s * MAXDEG + j];
                atomicOr(&row[t >> 5], 1u << (t & 31));
            }
        }
    }

    // ---- part B: per-node edge weight precompute (threads 0..NN-1) ----
    if (gtid < NN) {
        int i = gtid;
        float as = att_src[0], ad = att_dst[0];
        float hi  = g_h[i];
        float adh = ad * hi;
        float z   = as * hi + adh;
        float self = z > 0.f ? z : 0.2f * z;
        int dv = min(g_deg[i], MAXDEG);
        int base = i * MAXDEG;
        float m = self;
        float lg[MAXDEG > 16 ? 16 : MAXDEG];   // dv is ~8; spill-safe cap via loop below
        // first pass: max over all in-edge logits (recompute if dv>16)
        for (int j = 0; j < dv; j++) {
            float hs = g_nh[base + j];
            float zz = as * hs + adh;
            float l  = zz > 0.f ? zz : 0.2f * zz;
            if (j < 16) lg[j] = l;
            m = fmaxf(m, l);
        }
        for (int j = 0; j < dv; j++) {
            float hs = g_nh[base + j];
            float l;
            if (j < 16) l = lg[j];
            else { float zz = as * hs + adh; l = zz > 0.f ? zz : 0.2f * zz; }
            float w = __expf(l - m);
            float4 pk;
            pk.x = __int_as_float(g_nsrc[base + j]);
            pk.y = w;
            pk.z = w * hs;
            pk.w = 0.f;
            g_edge[base + j] = pk;
        }
        float sw = __expf(self - m);
        g_self[i] = make_float4(sw, sw * hi, __int_as_float(dv), hi);
    }
}

// ---------------- per-ego GAT + ego softmax + dense row write ----------------
__global__ void __launch_bounds__(128) k_ego(const float* __restrict__ bias,
                      float* __restrict__ out, int write_mask) {
    __shared__ unsigned row[ROWW];
    __shared__ int   list[512];
    __shared__ float vals[NN];
    __shared__ float red[5];
    __shared__ int   cnt;
    const int v = blockIdx.x;
    const int tid = threadIdx.x, lane = tid & 31, wp = tid >> 5;

    if (tid == 0) cnt = 0;
    if (tid < ROWW) row[tid] = __ldg(&g_rowM[(size_t)v * ROWW + tid]);
    __syncthreads();

    // write mask half of the row immediately (overlaps later compute)
    if (write_mask) {
        float4* mo4 = (float4*)(out + (size_t)NN * NN + (size_t)v * NN);
        for (int t = tid; t < NN / 4; t += 128) {
            int i0 = t * 4;
            unsigned w = row[i0 >> 5] >> (i0 & 31);
            float4 b;
            b.x = (w & 1u) ? 1.f : 0.f;
            b.y = (w & 2u) ? 1.f : 0.f;
            b.z = (w & 4u) ? 1.f : 0.f;
            b.w = (w & 8u) ? 1.f : 0.f;
            mo4[t] = b;
        }
    }

    // compact list of ego-node ids
    if (tid < ROWW) {
        unsigned m = row[tid];
        while (m) {
            int b = __ffs(m) - 1;
            m &= m - 1;
            int p = atomicAdd(&cnt, 1);
            if (p < 512) list[p] = tid * 32 + b;
        }
    }
    __syncthreads();
    const int n = min(cnt, 512);
    const float bi = bias[0];

    // pass 1: per-node GAT via precomputed exp weights (no exp, no branches)
    float mx = NEGBIG;
    for (int idx = tid; idx < n; idx += 128) {
        int i = list[idx];
        float4 sf = g_self[i];
        float denom = sf.x, num = sf.y;
        int dv = __float_as_int(sf.z);
        const float4* ep = g_edge + i * MAXDEG;
#pragma unroll 4
        for (int j = 0; j < dv; j++) {
            float4 pk = ep[j];
            int s = __float_as_int(pk.x);
            if ((row[s >> 5] >> (s & 31)) & 1u) {
                denom += pk.y;
                num   += pk.z;
            }
        }
        float gat = num / denom + bi;
        vals[i] = gat;
        mx = fmaxf(mx, gat);
    }
    // block-reduce max (4 warps)
#pragma unroll
    for (int off = 16; off; off >>= 1) mx = fmaxf(mx, __shfl_xor_sync(0xffffffffu, mx, off));
    if (lane == 0) red[wp] = mx;
    __syncthreads();
    mx = fmaxf(fmaxf(red[0], red[1]), fmaxf(red[2], red[3]));

    // pass 2: exp + block-reduce sum
    float sm = 0.f;
    for (int idx = tid; idx < n; idx += 128) {
        int i = list[idx];
        float e = __expf(vals[i] - mx);
        vals[i] = e;
        sm += e;
    }
#pragma unroll
    for (int off = 16; off; off >>= 1) sm += __shfl_xor_sync(0xffffffffu, sm, off);
    if (lane == 0) red[wp] = sm;
    __syncthreads();
    const float inv = 1.f / (red[0] + red[1] + red[2] + red[3]);
    __syncthreads();

    // pass 3: vectorized scores row write
    float4* so4 = (float4*)(out + (size_t)v * NN);
    for (int t = tid; t < NN / 4; t += 128) {
        int i0 = t * 4;
        unsigned w = row[i0 >> 5] >> (i0 & 31);
        float4 a;
        a.x = (w & 1u) ? vals[i0 + 0] * inv : 0.f;
        a.y = (w & 2u) ? vals[i0 + 1] * inv : 0.f;
        a.z = (w & 4u) ? vals[i0 + 2] * inv : 0.f;
        a.w = (w & 8u) ? vals[i0 + 3] * inv : 0.f;
        so4[t] = a;
    }
}

// ---------------- launch ----------------
extern "C" void kernel_launch(void* const* d_in, const int* in_sizes, int n_in,
                              void* d_out, int out_size) {
    // inputs: 0:x 1:x_orig 2:edge_index 3:batch 4:W2 5:att_src 6:att_dst 7:bias
    const float* x_orig  = (const float*)d_in[1];
    const int*   ei      = (const int*)d_in[2];
    const float* W2      = (const float*)d_in[4];
    const float* att_src = (const float*)d_in[5];
    const float* att_dst = (const float*)d_in[6];
    const float* bias    = (const float*)d_in[7];
    float* out = (float*)d_out;
    int write_mask = (out_size >= 2 * NN * NN) ? 1 : 0;

    k_h<<<NN / 8, 256>>>(x_orig, W2);             // h, zero deg + rowM
    k_scatter<<<EE / 256, 256>>>(ei);             // fixed-stride in-edge CSR
    k_hops_pre<<<NN / 8, 256>>>(att_src, att_dst);// masks + edge exp precompute
    k_ego<<<NN, 128>>>(bias, out, write_mask);    // GAT + softmax + row writes
}